// round 1
// baseline (speedup 1.0000x reference)
#include <cuda_runtime.h>

#define D 256
#define MAXN 50048
#define MAXE 400256
#define LN_EPS 1e-5f

// ---------------- scratch (static device globals; no allocation) ------------
__device__ float g_wsum[D * D];          // (W0+W1+W2)/3
__device__ float g_gfeat[MAXN * D];      // aggregated features (pre-GEMM)
__device__ float g_agg[MAXN * D];        // GEMM output (pre-LN)
__device__ int   g_deg[3 * MAXN];
__device__ int   g_offs[3 * MAXN];
__device__ int   g_cur[3 * MAXN];
__device__ int   g_bucket[3 * MAXE];

// ---------------- tiny elementwise: Wsum = (W0+W1+W2)/3 --------------------
__global__ void wsum_kernel(const float* __restrict__ W0,
                            const float* __restrict__ W1,
                            const float* __restrict__ W2) {
    int i = blockIdx.x * blockDim.x + threadIdx.x;
    if (i < D * D)
        g_wsum[i] = (W0[i] + W1[i] + W2[i]) * (1.0f / 3.0f);
}

// ---------------- zero counters --------------------------------------------
__global__ void zero_kernel(int N) {
    int i = blockIdx.x * blockDim.x + threadIdx.x;
    if (i < 3 * N) { g_deg[i] = 0; g_cur[i] = 0; }
}

// ---------------- histogram of dst per relation -----------------------------
__global__ void hist_kernel(const int* __restrict__ d0,
                            const int* __restrict__ d1,
                            const int* __restrict__ d2, int N, int E) {
    int i = blockIdx.x * blockDim.x + threadIdx.x;
    if (i >= 3 * E) return;
    int r = i / E, e = i - r * E;
    const int* ds = (r == 0) ? d0 : (r == 1) ? d1 : d2;
    atomicAdd(&g_deg[r * N + ds[e]], 1);
}

// ---------------- single-block exclusive scan over 3N ints ------------------
__global__ void scan_kernel(int total) {
    __shared__ int s[1024];
    __shared__ int carry;
    int tid = threadIdx.x;
    if (tid == 0) carry = 0;
    __syncthreads();
    for (int base = 0; base < total; base += 1024) {
        int i = base + tid;
        int v = (i < total) ? g_deg[i] : 0;
        s[tid] = v;
        __syncthreads();
        #pragma unroll
        for (int off = 1; off < 1024; off <<= 1) {
            int t = (tid >= off) ? s[tid - off] : 0;
            __syncthreads();
            s[tid] += t;
            __syncthreads();
        }
        int incl = s[tid];
        if (i < total) g_offs[i] = carry + incl - v;   // exclusive
        __syncthreads();
        if (tid == 1023) carry += s[1023];
        __syncthreads();
    }
}

// ---------------- scatter edge srcs into CSR buckets ------------------------
__global__ void scatter_kernel(const int* __restrict__ s0, const int* __restrict__ d0,
                               const int* __restrict__ s1, const int* __restrict__ d1,
                               const int* __restrict__ s2, const int* __restrict__ d2,
                               int N, int E) {
    int i = blockIdx.x * blockDim.x + threadIdx.x;
    if (i >= 3 * E) return;
    int r = i / E, e = i - r * E;
    const int* ss = (r == 0) ? s0 : (r == 1) ? s1 : s2;
    const int* ds = (r == 0) ? d0 : (r == 1) ? d1 : d2;
    int node = r * N + ds[e];
    int p = atomicAdd(&g_cur[node], 1);
    g_bucket[g_offs[node] + p] = ss[e];
}

// ---------------- aggregate: warp per node, mean over per-relation edges ----
__global__ void agg_kernel(const float* __restrict__ feat, int N) {
    int gwarp = (blockIdx.x * blockDim.x + threadIdx.x) >> 5;
    int lane = threadIdx.x & 31;
    if (gwarp >= N) return;
    float4 acc0 = make_float4(0.f, 0.f, 0.f, 0.f);
    float4 acc1 = make_float4(0.f, 0.f, 0.f, 0.f);
    #pragma unroll
    for (int r = 0; r < 3; r++) {
        int idx = r * N + gwarp;
        int off = g_offs[idx];
        int dg = g_deg[idx];
        float4 s0 = make_float4(0.f, 0.f, 0.f, 0.f);
        float4 s1 = make_float4(0.f, 0.f, 0.f, 0.f);
        for (int e = 0; e < dg; e++) {
            int src = g_bucket[off + e];
            const float4* row = (const float4*)(feat + (size_t)src * D);
            float4 v0 = row[lane];
            float4 v1 = row[32 + lane];
            s0.x += v0.x; s0.y += v0.y; s0.z += v0.z; s0.w += v0.w;
            s1.x += v1.x; s1.y += v1.y; s1.z += v1.z; s1.w += v1.w;
        }
        float sc = 1.0f / fmaxf((float)dg, 1.0f);
        acc0.x += s0.x * sc; acc0.y += s0.y * sc; acc0.z += s0.z * sc; acc0.w += s0.w * sc;
        acc1.x += s1.x * sc; acc1.y += s1.y * sc; acc1.z += s1.z * sc; acc1.w += s1.w * sc;
    }
    const float third = 1.0f / 3.0f;
    acc0.x *= third; acc0.y *= third; acc0.z *= third; acc0.w *= third;
    acc1.x *= third; acc1.y *= third; acc1.z *= third; acc1.w *= third;
    float4* orow = (float4*)(g_gfeat + (size_t)gwarp * D);
    orow[lane] = acc0;
    orow[32 + lane] = acc1;
}

// ---------------- SGEMM: C[M,256] = A[M,256] @ B[256,256] -------------------
#define BM 128
#define BN 128
#define BK 8
#define TM 8
#define TN 8
__global__ __launch_bounds__(256) void gemm_kernel(int M) {
    const float* __restrict__ A = g_gfeat;
    const float* __restrict__ B = g_wsum;
    float* __restrict__ C = g_agg;

    __shared__ float As[BK][BM];
    __shared__ float Bs[BK][BN];
    int tid = threadIdx.x;
    int tx = tid & 15, ty = tid >> 4;
    int rowBase = blockIdx.y * BM;
    int colBase = blockIdx.x * BN;

    float acc[TM][TN];
    #pragma unroll
    for (int i = 0; i < TM; i++)
        #pragma unroll
        for (int j = 0; j < TN; j++) acc[i][j] = 0.f;

    int aRow = tid >> 1;
    int aK = (tid & 1) * 4;
    int bK = tid >> 5;
    int bCol = (tid & 31) * 4;

    for (int k0 = 0; k0 < D; k0 += BK) {
        float4 av;
        int gr = rowBase + aRow;
        if (gr < M) av = *(const float4*)(A + (size_t)gr * D + k0 + aK);
        else av = make_float4(0.f, 0.f, 0.f, 0.f);
        As[aK + 0][aRow] = av.x;
        As[aK + 1][aRow] = av.y;
        As[aK + 2][aRow] = av.z;
        As[aK + 3][aRow] = av.w;
        *(float4*)(&Bs[bK][bCol]) = *(const float4*)(B + (size_t)(k0 + bK) * D + colBase + bCol);
        __syncthreads();
        #pragma unroll
        for (int k = 0; k < BK; k++) {
            float ar[TM], br[TN];
            #pragma unroll
            for (int i = 0; i < TM; i++) ar[i] = As[k][ty * TM + i];
            #pragma unroll
            for (int j = 0; j < TN; j++) br[j] = Bs[k][tx * TN + j];
            #pragma unroll
            for (int i = 0; i < TM; i++)
                #pragma unroll
                for (int j = 0; j < TN; j++)
                    acc[i][j] += ar[i] * br[j];
        }
        __syncthreads();
    }
    #pragma unroll
    for (int i = 0; i < TM; i++) {
        int gr = rowBase + ty * TM + i;
        if (gr < M) {
            float4* cp = (float4*)(C + (size_t)gr * D + colBase + tx * TN);
            cp[0] = make_float4(acc[i][0], acc[i][1], acc[i][2], acc[i][3]);
            cp[1] = make_float4(acc[i][4], acc[i][5], acc[i][6], acc[i][7]);
        }
    }
}

// ---------------- ReLU + LayerNorm: warp per row ----------------------------
__global__ void ln_kernel(const float* __restrict__ gamma,
                          const float* __restrict__ beta,
                          float* __restrict__ out, int N) {
    int row = (blockIdx.x * blockDim.x + threadIdx.x) >> 5;
    int lane = threadIdx.x & 31;
    if (row >= N) return;
    const float4* a = (const float4*)(g_agg + (size_t)row * D);
    float4 v0 = a[lane];
    float4 v1 = a[32 + lane];
    v0.x = fmaxf(v0.x, 0.f); v0.y = fmaxf(v0.y, 0.f);
    v0.z = fmaxf(v0.z, 0.f); v0.w = fmaxf(v0.w, 0.f);
    v1.x = fmaxf(v1.x, 0.f); v1.y = fmaxf(v1.y, 0.f);
    v1.z = fmaxf(v1.z, 0.f); v1.w = fmaxf(v1.w, 0.f);

    float s = v0.x + v0.y + v0.z + v0.w + v1.x + v1.y + v1.z + v1.w;
    float ss = v0.x * v0.x + v0.y * v0.y + v0.z * v0.z + v0.w * v0.w
             + v1.x * v1.x + v1.y * v1.y + v1.z * v1.z + v1.w * v1.w;
    #pragma unroll
    for (int o = 16; o > 0; o >>= 1) {
        s += __shfl_xor_sync(0xffffffffu, s, o);
        ss += __shfl_xor_sync(0xffffffffu, ss, o);
    }
    float mu = s * (1.0f / D);
    float var = ss * (1.0f / D) - mu * mu;
    float rs = rsqrtf(var + LN_EPS);

    const float4* g4 = (const float4*)gamma;
    const float4* b4 = (const float4*)beta;
    float4 g0 = g4[lane], g1 = g4[32 + lane];
    float4 b0 = b4[lane], b1 = b4[32 + lane];
    float4 o0, o1;
    o0.x = (v0.x - mu) * rs * g0.x + b0.x;
    o0.y = (v0.y - mu) * rs * g0.y + b0.y;
    o0.z = (v0.z - mu) * rs * g0.z + b0.z;
    o0.w = (v0.w - mu) * rs * g0.w + b0.w;
    o1.x = (v1.x - mu) * rs * g1.x + b1.x;
    o1.y = (v1.y - mu) * rs * g1.y + b1.y;
    o1.z = (v1.z - mu) * rs * g1.z + b1.z;
    o1.w = (v1.w - mu) * rs * g1.w + b1.w;
    float4* orow = (float4*)(out + (size_t)row * D);
    orow[lane] = o0;
    orow[32 + lane] = o1;
}

// ---------------- launch ----------------------------------------------------
extern "C" void kernel_launch(void* const* d_in, const int* in_sizes, int n_in,
                              void* d_out, int out_size) {
    const float* feat = (const float*)d_in[0];
    const float* W0 = (const float*)d_in[1];
    const float* W1 = (const float*)d_in[2];
    const float* W2 = (const float*)d_in[3];
    // d_in[4..6] = a0,a1,a2: softmax over size-1 tensors is identically 1,
    // so the mixing weights are always [1/3,1/3,1/3] independent of values.
    const float* gamma = (const float*)d_in[7];
    const float* beta = (const float*)d_in[8];
    const int* src0 = (const int*)d_in[9];
    const int* dst0 = (const int*)d_in[10];
    const int* src1 = (const int*)d_in[11];
    const int* dst1 = (const int*)d_in[12];
    const int* src2 = (const int*)d_in[13];
    const int* dst2 = (const int*)d_in[14];
    float* out = (float*)d_out;

    int N = in_sizes[0] / D;
    int E = in_sizes[9];

    wsum_kernel<<<(D * D + 255) / 256, 256>>>(W0, W1, W2);
    zero_kernel<<<(3 * N + 255) / 256, 256>>>(N);
    hist_kernel<<<(3 * E + 255) / 256, 256>>>(dst0, dst1, dst2, N, E);
    scan_kernel<<<1, 1024>>>(3 * N);
    scatter_kernel<<<(3 * E + 255) / 256, 256>>>(src0, dst0, src1, dst1, src2, dst2, N, E);
    agg_kernel<<<(N + 7) / 8, 256>>>(feat, N);
    dim3 ggrid(D / BN, (N + BM - 1) / BM);
    gemm_kernel<<<ggrid, 256>>>(N);
    ln_kernel<<<(N + 7) / 8, 256>>>(gamma, beta, out, N);
}

// round 2
// speedup vs baseline: 1.5811x; 1.5811x over previous
#include <cuda_runtime.h>

#define D 256
#define MAXN 50048
#define MAXE 400256
#define LN_EPS 1e-5f
#define SCAN_B 1024

// ---------------- scratch (static device globals; no allocation) ------------
__device__ float g_wsum[D * D];          // (W0+W1+W2)/3
__device__ float g_gfeat[MAXN * D];      // aggregated features (pre-GEMM)
__device__ float g_agg[MAXN * D];        // GEMM output (pre-LN)
__device__ int   g_deg[3 * MAXN];
__device__ int   g_offs[3 * MAXN];
__device__ int   g_cur[3 * MAXN];
__device__ int   g_bucket[3 * MAXE];
__device__ int   g_blocksum[1024];
__device__ int   g_blockoff[1024];

// ---------------- tiny elementwise: Wsum = (W0+W1+W2)/3 --------------------
__global__ void wsum_kernel(const float* __restrict__ W0,
                            const float* __restrict__ W1,
                            const float* __restrict__ W2) {
    int i = blockIdx.x * blockDim.x + threadIdx.x;
    if (i < D * D)
        g_wsum[i] = (W0[i] + W1[i] + W2[i]) * (1.0f / 3.0f);
}

// ---------------- zero degree counters --------------------------------------
__global__ void zero_kernel(int N) {
    int i = blockIdx.x * blockDim.x + threadIdx.x;
    if (i < 3 * N) g_deg[i] = 0;
}

// ---------------- histogram of dst per relation -----------------------------
__global__ void hist_kernel(const int* __restrict__ d0,
                            const int* __restrict__ d1,
                            const int* __restrict__ d2, int N, int E) {
    int i = blockIdx.x * blockDim.x + threadIdx.x;
    if (i >= 3 * E) return;
    int r = i / E, e = i - r * E;
    const int* ds = (r == 0) ? d0 : (r == 1) ? d1 : d2;
    atomicAdd(&g_deg[r * N + ds[e]], 1);
}

// ---------------- multi-block exclusive scan, phase 1 -----------------------
// Each block scans SCAN_B elements with warp shuffles; writes per-block sum.
__global__ __launch_bounds__(SCAN_B) void scan_phase1(int total) {
    __shared__ int warpsum[SCAN_B / 32];
    int tid = threadIdx.x;
    int lane = tid & 31;
    int wid = tid >> 5;
    int i = blockIdx.x * SCAN_B + tid;
    int v = (i < total) ? g_deg[i] : 0;

    // inclusive warp scan
    int incl = v;
    #pragma unroll
    for (int o = 1; o < 32; o <<= 1) {
        int t = __shfl_up_sync(0xffffffffu, incl, o);
        if (lane >= o) incl += t;
    }
    if (lane == 31) warpsum[wid] = incl;
    __syncthreads();
    if (wid == 0) {
        int w = (lane < SCAN_B / 32) ? warpsum[lane] : 0;
        #pragma unroll
        for (int o = 1; o < 32; o <<= 1) {
            int t = __shfl_up_sync(0xffffffffu, w, o);
            if (lane >= o) w += t;
        }
        if (lane < SCAN_B / 32) warpsum[lane] = w;   // inclusive over warps
    }
    __syncthreads();
    int warpoff = (wid == 0) ? 0 : warpsum[wid - 1];
    int excl = warpoff + incl - v;
    if (i < total) g_offs[i] = excl;
    if (tid == SCAN_B - 1) g_blocksum[blockIdx.x] = excl + v;  // block total
}

// ---------------- phase 2: scan block sums (single block, <=1024) -----------
__global__ __launch_bounds__(1024) void scan_phase2(int nblocks) {
    __shared__ int warpsum[32];
    int tid = threadIdx.x;
    int lane = tid & 31;
    int wid = tid >> 5;
    int v = (tid < nblocks) ? g_blocksum[tid] : 0;
    int incl = v;
    #pragma unroll
    for (int o = 1; o < 32; o <<= 1) {
        int t = __shfl_up_sync(0xffffffffu, incl, o);
        if (lane >= o) incl += t;
    }
    if (lane == 31) warpsum[wid] = incl;
    __syncthreads();
    if (wid == 0) {
        int w = (lane < 32) ? warpsum[lane] : 0;
        #pragma unroll
        for (int o = 1; o < 32; o <<= 1) {
            int t = __shfl_up_sync(0xffffffffu, w, o);
            if (lane >= o) w += t;
        }
        warpsum[lane] = w;
    }
    __syncthreads();
    int warpoff = (wid == 0) ? 0 : warpsum[wid - 1];
    if (tid < nblocks) g_blockoff[tid] = warpoff + incl - v;   // exclusive
}

// ---------------- phase 3: add block offsets; init cursor --------------------
__global__ void scan_phase3(int total) {
    int i = blockIdx.x * SCAN_B + threadIdx.x;
    if (i >= total) return;
    int o = g_offs[i] + g_blockoff[blockIdx.x];
    g_offs[i] = o;
    g_cur[i] = o;
}

// ---------------- scatter edge srcs into CSR buckets ------------------------
__global__ void scatter_kernel(const int* __restrict__ s0, const int* __restrict__ d0,
                               const int* __restrict__ s1, const int* __restrict__ d1,
                               const int* __restrict__ s2, const int* __restrict__ d2,
                               int N, int E) {
    int i = blockIdx.x * blockDim.x + threadIdx.x;
    if (i >= 3 * E) return;
    int r = i / E, e = i - r * E;
    const int* ss = (r == 0) ? s0 : (r == 1) ? s1 : s2;
    const int* ds = (r == 0) ? d0 : (r == 1) ? d1 : d2;
    int node = r * N + ds[e];
    int p = atomicAdd(&g_cur[node], 1);
    g_bucket[p] = ss[e];
}

// ---------------- aggregate: warp per node, mean over per-relation edges ----
__global__ void agg_kernel(const float* __restrict__ feat, int N) {
    int gwarp = (blockIdx.x * blockDim.x + threadIdx.x) >> 5;
    int lane = threadIdx.x & 31;
    if (gwarp >= N) return;
    float4 acc0 = make_float4(0.f, 0.f, 0.f, 0.f);
    float4 acc1 = make_float4(0.f, 0.f, 0.f, 0.f);
    #pragma unroll
    for (int r = 0; r < 3; r++) {
        int idx = r * N + gwarp;
        int off = g_offs[idx];
        int dg = g_deg[idx];
        float4 s0 = make_float4(0.f, 0.f, 0.f, 0.f);
        float4 s1 = make_float4(0.f, 0.f, 0.f, 0.f);
        for (int e = 0; e < dg; e++) {
            int src = g_bucket[off + e];
            const float4* row = (const float4*)(feat + (size_t)src * D);
            float4 v0 = row[lane];
            float4 v1 = row[32 + lane];
            s0.x += v0.x; s0.y += v0.y; s0.z += v0.z; s0.w += v0.w;
            s1.x += v1.x; s1.y += v1.y; s1.z += v1.z; s1.w += v1.w;
        }
        float sc = 1.0f / fmaxf((float)dg, 1.0f);
        acc0.x += s0.x * sc; acc0.y += s0.y * sc; acc0.z += s0.z * sc; acc0.w += s0.w * sc;
        acc1.x += s1.x * sc; acc1.y += s1.y * sc; acc1.z += s1.z * sc; acc1.w += s1.w * sc;
    }
    const float third = 1.0f / 3.0f;
    acc0.x *= third; acc0.y *= third; acc0.z *= third; acc0.w *= third;
    acc1.x *= third; acc1.y *= third; acc1.z *= third; acc1.w *= third;
    float4* orow = (float4*)(g_gfeat + (size_t)gwarp * D);
    orow[lane] = acc0;
    orow[32 + lane] = acc1;
}

// ---------------- SGEMM: C[M,256] = A[M,256] @ B[256,256] -------------------
#define BM 128
#define BN 128
#define BK 8
#define TM 8
#define TN 8
__global__ __launch_bounds__(256) void gemm_kernel(int M) {
    const float* __restrict__ A = g_gfeat;
    const float* __restrict__ B = g_wsum;
    float* __restrict__ C = g_agg;

    __shared__ float As[BK][BM];
    __shared__ float Bs[BK][BN];
    int tid = threadIdx.x;
    int tx = tid & 15, ty = tid >> 4;
    int rowBase = blockIdx.y * BM;
    int colBase = blockIdx.x * BN;

    float acc[TM][TN];
    #pragma unroll
    for (int i = 0; i < TM; i++)
        #pragma unroll
        for (int j = 0; j < TN; j++) acc[i][j] = 0.f;

    int aRow = tid >> 1;
    int aK = (tid & 1) * 4;
    int bK = tid >> 5;
    int bCol = (tid & 31) * 4;

    for (int k0 = 0; k0 < D; k0 += BK) {
        float4 av;
        int gr = rowBase + aRow;
        if (gr < M) av = *(const float4*)(A + (size_t)gr * D + k0 + aK);
        else av = make_float4(0.f, 0.f, 0.f, 0.f);
        As[aK + 0][aRow] = av.x;
        As[aK + 1][aRow] = av.y;
        As[aK + 2][aRow] = av.z;
        As[aK + 3][aRow] = av.w;
        *(float4*)(&Bs[bK][bCol]) = *(const float4*)(B + (size_t)(k0 + bK) * D + colBase + bCol);
        __syncthreads();
        #pragma unroll
        for (int k = 0; k < BK; k++) {
            float ar[TM], br[TN];
            #pragma unroll
            for (int i = 0; i < TM; i++) ar[i] = As[k][ty * TM + i];
            #pragma unroll
            for (int j = 0; j < TN; j++) br[j] = Bs[k][tx * TN + j];
            #pragma unroll
            for (int i = 0; i < TM; i++)
                #pragma unroll
                for (int j = 0; j < TN; j++)
                    acc[i][j] += ar[i] * br[j];
        }
        __syncthreads();
    }
    #pragma unroll
    for (int i = 0; i < TM; i++) {
        int gr = rowBase + ty * TM + i;
        if (gr < M) {
            float4* cp = (float4*)(C + (size_t)gr * D + colBase + tx * TN);
            cp[0] = make_float4(acc[i][0], acc[i][1], acc[i][2], acc[i][3]);
            cp[1] = make_float4(acc[i][4], acc[i][5], acc[i][6], acc[i][7]);
        }
    }
}

// ---------------- ReLU + LayerNorm: warp per row ----------------------------
__global__ void ln_kernel(const float* __restrict__ gamma,
                          const float* __restrict__ beta,
                          float* __restrict__ out, int N) {
    int row = (blockIdx.x * blockDim.x + threadIdx.x) >> 5;
    int lane = threadIdx.x & 31;
    if (row >= N) return;
    const float4* a = (const float4*)(g_agg + (size_t)row * D);
    float4 v0 = a[lane];
    float4 v1 = a[32 + lane];
    v0.x = fmaxf(v0.x, 0.f); v0.y = fmaxf(v0.y, 0.f);
    v0.z = fmaxf(v0.z, 0.f); v0.w = fmaxf(v0.w, 0.f);
    v1.x = fmaxf(v1.x, 0.f); v1.y = fmaxf(v1.y, 0.f);
    v1.z = fmaxf(v1.z, 0.f); v1.w = fmaxf(v1.w, 0.f);

    float s = v0.x + v0.y + v0.z + v0.w + v1.x + v1.y + v1.z + v1.w;
    float ss = v0.x * v0.x + v0.y * v0.y + v0.z * v0.z + v0.w * v0.w
             + v1.x * v1.x + v1.y * v1.y + v1.z * v1.z + v1.w * v1.w;
    #pragma unroll
    for (int o = 16; o > 0; o >>= 1) {
        s += __shfl_xor_sync(0xffffffffu, s, o);
        ss += __shfl_xor_sync(0xffffffffu, ss, o);
    }
    float mu = s * (1.0f / D);
    float var = ss * (1.0f / D) - mu * mu;
    float rs = rsqrtf(var + LN_EPS);

    const float4* g4 = (const float4*)gamma;
    const float4* b4 = (const float4*)beta;
    float4 g0 = g4[lane], g1 = g4[32 + lane];
    float4 b0 = b4[lane], b1 = b4[32 + lane];
    float4 o0, o1;
    o0.x = (v0.x - mu) * rs * g0.x + b0.x;
    o0.y = (v0.y - mu) * rs * g0.y + b0.y;
    o0.z = (v0.z - mu) * rs * g0.z + b0.z;
    o0.w = (v0.w - mu) * rs * g0.w + b0.w;
    o1.x = (v1.x - mu) * rs * g1.x + b1.x;
    o1.y = (v1.y - mu) * rs * g1.y + b1.y;
    o1.z = (v1.z - mu) * rs * g1.z + b1.z;
    o1.w = (v1.w - mu) * rs * g1.w + b1.w;
    float4* orow = (float4*)(out + (size_t)row * D);
    orow[lane] = o0;
    orow[32 + lane] = o1;
}

// ---------------- launch ----------------------------------------------------
extern "C" void kernel_launch(void* const* d_in, const int* in_sizes, int n_in,
                              void* d_out, int out_size) {
    const float* feat = (const float*)d_in[0];
    const float* W0 = (const float*)d_in[1];
    const float* W1 = (const float*)d_in[2];
    const float* W2 = (const float*)d_in[3];
    // d_in[4..6] = a0,a1,a2: softmax over size-1 tensors is identically 1,
    // so the mixing weights are always [1/3,1/3,1/3] independent of values.
    const float* gamma = (const float*)d_in[7];
    const float* beta = (const float*)d_in[8];
    const int* src0 = (const int*)d_in[9];
    const int* dst0 = (const int*)d_in[10];
    const int* src1 = (const int*)d_in[11];
    const int* dst1 = (const int*)d_in[12];
    const int* src2 = (const int*)d_in[13];
    const int* dst2 = (const int*)d_in[14];
    float* out = (float*)d_out;

    int N = in_sizes[0] / D;
    int E = in_sizes[9];
    int total = 3 * N;
    int nblocks = (total + SCAN_B - 1) / SCAN_B;

    wsum_kernel<<<(D * D + 255) / 256, 256>>>(W0, W1, W2);
    zero_kernel<<<(total + 255) / 256, 256>>>(N);
    hist_kernel<<<(3 * E + 255) / 256, 256>>>(dst0, dst1, dst2, N, E);
    scan_phase1<<<nblocks, SCAN_B>>>(total);
    scan_phase2<<<1, 1024>>>(nblocks);
    scan_phase3<<<nblocks, SCAN_B>>>(total);
    scatter_kernel<<<(3 * E + 255) / 256, 256>>>(src0, dst0, src1, dst1, src2, dst2, N, E);
    agg_kernel<<<(N + 7) / 8, 256>>>(feat, N);
    dim3 ggrid(D / BN, (N + BM - 1) / BM);
    gemm_kernel<<<ggrid, 256>>>(N);
    ln_kernel<<<(N + 7) / 8, 256>>>(gamma, beta, out, N);
}

// round 4
// speedup vs baseline: 1.8252x; 1.1544x over previous
#include <cuda_runtime.h>
#include <cuda_fp16.h>

#define D 256
#define MAXN 50048
#define MAXE 400256
#define LN_EPS 1e-5f
#define SCAN_B 1024

// ---------------- scratch (static device globals; no allocation) ------------
__device__ float   g_wsum[D * D];          // (W0+W1+W2)/3
__device__ float   g_gfeat[MAXN * D];      // aggregated features (pre-GEMM)
__device__ __half2 g_feat16[MAXN * D / 2]; // fp16 copy of feat for the gather
__device__ int     g_deg[3 * MAXN];
__device__ int     g_offs[3 * MAXN];
__device__ int     g_cur[3 * MAXN];
__device__ int     g_bucket[3 * MAXE];
__device__ int     g_blocksum[1024];
__device__ int     g_blockoff[1024];

// ---------------- tiny elementwise: Wsum = (W0+W1+W2)/3 --------------------
__global__ void wsum_kernel(const float* __restrict__ W0,
                            const float* __restrict__ W1,
                            const float* __restrict__ W2) {
    int i = blockIdx.x * blockDim.x + threadIdx.x;
    if (i < D * D)
        g_wsum[i] = (W0[i] + W1[i] + W2[i]) * (1.0f / 3.0f);
}

// ---------------- fp32 -> fp16 conversion of feat ---------------------------
__global__ void tohalf_kernel(const float* __restrict__ feat, int total2) {
    int i = blockIdx.x * blockDim.x + threadIdx.x;
    if (i < total2) {
        float2 v = ((const float2*)feat)[i];
        g_feat16[i] = __floats2half2_rn(v.x, v.y);
    }
}

// ---------------- zero degree counters --------------------------------------
__global__ void zero_kernel(int N) {
    int i = blockIdx.x * blockDim.x + threadIdx.x;
    if (i < 3 * N) g_deg[i] = 0;
}

// ---------------- histogram of dst per relation -----------------------------
__global__ void hist_kernel(const int* __restrict__ d0,
                            const int* __restrict__ d1,
                            const int* __restrict__ d2, int N, int E) {
    int i = blockIdx.x * blockDim.x + threadIdx.x;
    if (i >= 3 * E) return;
    int r = i / E, e = i - r * E;
    const int* ds = (r == 0) ? d0 : (r == 1) ? d1 : d2;
    atomicAdd(&g_deg[r * N + ds[e]], 1);
}

// ---------------- multi-block exclusive scan, phase 1 -----------------------
__global__ __launch_bounds__(SCAN_B) void scan_phase1(int total) {
    __shared__ int warpsum[SCAN_B / 32];
    int tid = threadIdx.x;
    int lane = tid & 31;
    int wid = tid >> 5;
    int i = blockIdx.x * SCAN_B + tid;
    int v = (i < total) ? g_deg[i] : 0;

    int incl = v;
    #pragma unroll
    for (int o = 1; o < 32; o <<= 1) {
        int t = __shfl_up_sync(0xffffffffu, incl, o);
        if (lane >= o) incl += t;
    }
    if (lane == 31) warpsum[wid] = incl;
    __syncthreads();
    if (wid == 0) {
        int w = (lane < SCAN_B / 32) ? warpsum[lane] : 0;
        #pragma unroll
        for (int o = 1; o < 32; o <<= 1) {
            int t = __shfl_up_sync(0xffffffffu, w, o);
            if (lane >= o) w += t;
        }
        if (lane < SCAN_B / 32) warpsum[lane] = w;
    }
    __syncthreads();
    int warpoff = (wid == 0) ? 0 : warpsum[wid - 1];
    int excl = warpoff + incl - v;
    if (i < total) g_offs[i] = excl;
    if (tid == SCAN_B - 1) g_blocksum[blockIdx.x] = excl + v;
}

// ---------------- phase 2: scan block sums -----------------------------------
__global__ __launch_bounds__(1024) void scan_phase2(int nblocks) {
    __shared__ int warpsum[32];
    int tid = threadIdx.x;
    int lane = tid & 31;
    int wid = tid >> 5;
    int v = (tid < nblocks) ? g_blocksum[tid] : 0;
    int incl = v;
    #pragma unroll
    for (int o = 1; o < 32; o <<= 1) {
        int t = __shfl_up_sync(0xffffffffu, incl, o);
        if (lane >= o) incl += t;
    }
    if (lane == 31) warpsum[wid] = incl;
    __syncthreads();
    if (wid == 0) {
        int w = warpsum[lane];
        #pragma unroll
        for (int o = 1; o < 32; o <<= 1) {
            int t = __shfl_up_sync(0xffffffffu, w, o);
            if (lane >= o) w += t;
        }
        warpsum[lane] = w;
    }
    __syncthreads();
    int warpoff = (wid == 0) ? 0 : warpsum[wid - 1];
    if (tid < nblocks) g_blockoff[tid] = warpoff + incl - v;
}

// ---------------- phase 3: add block offsets; init cursor --------------------
__global__ void scan_phase3(int total) {
    int i = blockIdx.x * SCAN_B + threadIdx.x;
    if (i >= total) return;
    int o = g_offs[i] + g_blockoff[blockIdx.x];
    g_offs[i] = o;
    g_cur[i] = o;
}

// ---------------- scatter edge srcs into CSR buckets ------------------------
__global__ void scatter_kernel(const int* __restrict__ s0, const int* __restrict__ d0,
                               const int* __restrict__ s1, const int* __restrict__ d1,
                               const int* __restrict__ s2, const int* __restrict__ d2,
                               int N, int E) {
    int i = blockIdx.x * blockDim.x + threadIdx.x;
    if (i >= 3 * E) return;
    int r = i / E, e = i - r * E;
    const int* ss = (r == 0) ? s0 : (r == 1) ? s1 : s2;
    const int* ds = (r == 0) ? d0 : (r == 1) ? d1 : d2;
    int node = r * N + ds[e];
    int p = atomicAdd(&g_cur[node], 1);
    g_bucket[p] = ss[e];
}

// ---------------- aggregate: warp per node, fp16 rows, fp32 accumulate ------
__global__ void agg_kernel(int N) {
    int gwarp = (blockIdx.x * blockDim.x + threadIdx.x) >> 5;
    int lane = threadIdx.x & 31;
    if (gwarp >= N) return;
    float acc[8] = {0.f, 0.f, 0.f, 0.f, 0.f, 0.f, 0.f, 0.f};
    #pragma unroll
    for (int r = 0; r < 3; r++) {
        int idx = r * N + gwarp;
        int off = g_offs[idx];
        int dg = g_deg[idx];
        float s[8] = {0.f, 0.f, 0.f, 0.f, 0.f, 0.f, 0.f, 0.f};
        for (int e = 0; e < dg; e++) {
            int src = g_bucket[off + e];
            // row = 128 half2; lane owns half2[4*lane .. 4*lane+3] = cols 8*lane..8*lane+7
            const int4* row = (const int4*)(g_feat16 + (size_t)src * (D / 2));
            int4 v = row[lane];
            __half2 h0 = *(__half2*)&v.x;
            __half2 h1 = *(__half2*)&v.y;
            __half2 h2 = *(__half2*)&v.z;
            __half2 h3 = *(__half2*)&v.w;
            float2 f0 = __half22float2(h0);
            float2 f1 = __half22float2(h1);
            float2 f2 = __half22float2(h2);
            float2 f3 = __half22float2(h3);
            s[0] += f0.x; s[1] += f0.y; s[2] += f1.x; s[3] += f1.y;
            s[4] += f2.x; s[5] += f2.y; s[6] += f3.x; s[7] += f3.y;
        }
        float sc = 1.0f / fmaxf((float)dg, 1.0f);
        #pragma unroll
        for (int k = 0; k < 8; k++) acc[k] += s[k] * sc;
    }
    const float third = 1.0f / 3.0f;
    float4 o0 = make_float4(acc[0] * third, acc[1] * third, acc[2] * third, acc[3] * third);
    float4 o1 = make_float4(acc[4] * third, acc[5] * third, acc[6] * third, acc[7] * third);
    float4* orow = (float4*)(g_gfeat + (size_t)gwarp * D + lane * 8);
    orow[0] = o0;
    orow[1] = o1;
}

// ---------------- fused SGEMM + ReLU + LayerNorm -----------------------------
// C[M,256] = A[M,256] @ B[256,256]; each block owns 64 full rows.
// 256 threads: ty = warp (8 rows of 8), tx = lane (8 cols of 8).
#define GBM 64
#define GBK 16
__global__ __launch_bounds__(256) void gemm_ln_kernel(const float* __restrict__ gamma,
                                                      const float* __restrict__ beta,
                                                      float* __restrict__ out, int M) {
    const float* __restrict__ A = g_gfeat;
    const float* __restrict__ B = g_wsum;

    __shared__ float As[GBK][GBM];
    __shared__ float Bs[GBK][D];

    int tid = threadIdx.x;
    int tx = tid & 31;        // 0..31 -> cols tx*8 .. tx*8+7
    int ty = tid >> 5;        // 0..7  -> rows ty*8 .. ty*8+7
    int rowBase = blockIdx.x * GBM;

    float acc[8][8];
    #pragma unroll
    for (int i = 0; i < 8; i++)
        #pragma unroll
        for (int j = 0; j < 8; j++) acc[i][j] = 0.f;

    int aRow = tid >> 2;          // 0..63
    int aK = (tid & 3) * 4;       // 0,4,8,12

    for (int k0 = 0; k0 < D; k0 += GBK) {
        int gr = rowBase + aRow;
        float4 av = (gr < M) ? *(const float4*)(A + (size_t)gr * D + k0 + aK)
                             : make_float4(0.f, 0.f, 0.f, 0.f);
        As[aK + 0][aRow] = av.x;
        As[aK + 1][aRow] = av.y;
        As[aK + 2][aRow] = av.z;
        As[aK + 3][aRow] = av.w;
        #pragma unroll
        for (int j = 0; j < 4; j++) {
            int p = tid + 256 * j;          // 0..1023
            int bk = p >> 6;                // 0..15
            int bc = (p & 63) * 4;          // 0..252
            *(float4*)&Bs[bk][bc] = *(const float4*)(B + (size_t)(k0 + bk) * D + bc);
        }
        __syncthreads();
        #pragma unroll
        for (int k = 0; k < GBK; k++) {
            float4 a0 = *(float4*)&As[k][ty * 8];
            float4 a1 = *(float4*)&As[k][ty * 8 + 4];
            float4 b0 = *(float4*)&Bs[k][tx * 8];
            float4 b1 = *(float4*)&Bs[k][tx * 8 + 4];
            float ar[8] = {a0.x, a0.y, a0.z, a0.w, a1.x, a1.y, a1.z, a1.w};
            float br[8] = {b0.x, b0.y, b0.z, b0.w, b1.x, b1.y, b1.z, b1.w};
            #pragma unroll
            for (int i = 0; i < 8; i++)
                #pragma unroll
                for (int j = 0; j < 8; j++)
                    acc[i][j] += ar[i] * br[j];
        }
        __syncthreads();
    }

    // ---- epilogue: ReLU + LayerNorm per row (warp = 8 rows, lane = 8 cols) --
    const float4* g4 = (const float4*)(gamma + tx * 8);
    const float4* b4 = (const float4*)(beta + tx * 8);
    float4 gm0 = g4[0], gm1 = g4[1];
    float4 bt0 = b4[0], bt1 = b4[1];

    #pragma unroll
    for (int i = 0; i < 8; i++) {
        #pragma unroll
        for (int j = 0; j < 8; j++) acc[i][j] = fmaxf(acc[i][j], 0.f);
        float s = 0.f, ss = 0.f;
        #pragma unroll
        for (int j = 0; j < 8; j++) { s += acc[i][j]; ss += acc[i][j] * acc[i][j]; }
        #pragma unroll
        for (int o = 16; o > 0; o >>= 1) {
            s += __shfl_xor_sync(0xffffffffu, s, o);
            ss += __shfl_xor_sync(0xffffffffu, ss, o);
        }
        float mu = s * (1.0f / D);
        float var = ss * (1.0f / D) - mu * mu;
        float rs = rsqrtf(var + LN_EPS);

        int gr = rowBase + ty * 8 + i;
        if (gr < M) {
            float4 o0, o1;
            o0.x = (acc[i][0] - mu) * rs * gm0.x + bt0.x;
            o0.y = (acc[i][1] - mu) * rs * gm0.y + bt0.y;
            o0.z = (acc[i][2] - mu) * rs * gm0.z + bt0.z;
            o0.w = (acc[i][3] - mu) * rs * gm0.w + bt0.w;
            o1.x = (acc[i][4] - mu) * rs * gm1.x + bt1.x;
            o1.y = (acc[i][5] - mu) * rs * gm1.y + bt1.y;
            o1.z = (acc[i][6] - mu) * rs * gm1.z + bt1.z;
            o1.w = (acc[i][7] - mu) * rs * gm1.w + bt1.w;
            float4* op = (float4*)(out + (size_t)gr * D + tx * 8);
            op[0] = o0;
            op[1] = o1;
        }
    }
}

// ---------------- launch ----------------------------------------------------
extern "C" void kernel_launch(void* const* d_in, const int* in_sizes, int n_in,
                              void* d_out, int out_size) {
    const float* feat = (const float*)d_in[0];
    const float* W0 = (const float*)d_in[1];
    const float* W1 = (const float*)d_in[2];
    const float* W2 = (const float*)d_in[3];
    // d_in[4..6] = a0,a1,a2: softmax over size-1 tensors is identically 1,
    // so the mixing weights are always [1/3,1/3,1/3] independent of values.
    const float* gamma = (const float*)d_in[7];
    const float* beta = (const float*)d_in[8];
    const int* src0 = (const int*)d_in[9];
    const int* dst0 = (const int*)d_in[10];
    const int* src1 = (const int*)d_in[11];
    const int* dst1 = (const int*)d_in[12];
    const int* src2 = (const int*)d_in[13];
    const int* dst2 = (const int*)d_in[14];
    float* out = (float*)d_out;

    int N = in_sizes[0] / D;
    int E = in_sizes[9];
    int total = 3 * N;
    int nblocks = (total + SCAN_B - 1) / SCAN_B;
    int total2 = N * D / 2;

    wsum_kernel<<<(D * D + 255) / 256, 256>>>(W0, W1, W2);
    tohalf_kernel<<<(total2 + 255) / 256, 256>>>(feat, total2);
    zero_kernel<<<(total + 255) / 256, 256>>>(N);
    hist_kernel<<<(3 * E + 255) / 256, 256>>>(dst0, dst1, dst2, N, E);
    scan_phase1<<<nblocks, SCAN_B>>>(total);
    scan_phase2<<<1, 1024>>>(nblocks);
    scan_phase3<<<nblocks, SCAN_B>>>(total);
    scatter_kernel<<<(3 * E + 255) / 256, 256>>>(src0, dst0, src1, dst1, src2, dst2, N, E);
    agg_kernel<<<(N + 7) / 8, 256>>>(N);
    gemm_ln_kernel<<<(N + GBM - 1) / GBM, 256>>>(gamma, beta, out, N);
}

// round 5
// speedup vs baseline: 2.7510x; 1.5073x over previous
#include <cuda_runtime.h>
#include <cuda_fp16.h>

#define D 256
#define MAXN 50048
#define MAXE 400256
#define LN_EPS 1e-5f
#define SCAN_B 1024

// ---------------- scratch (static device globals; no allocation) ------------
__device__ __half  g_w16t[D * D];          // (W0+W1+W2)/3, TRANSPOSED [n][k], fp16
__device__ __half  g_afeat16[MAXN * D];    // aggregated features, fp16 (GEMM A)
__device__ __half2 g_feat16[MAXN * D / 2]; // fp16 copy of feat for the gather
__device__ int     g_deg[3 * MAXN];
__device__ int     g_offs[3 * MAXN];
__device__ int     g_cur[3 * MAXN];
__device__ int     g_bucket[3 * MAXE];
__device__ int     g_blocksum[1024];
__device__ int     g_blockoff[1024];

// ---------------- Wsum^T in fp16: g_w16t[n*D+k] = (W0+W1+W2)[k*D+n]/3 -------
__global__ void wsumT_kernel(const float* __restrict__ W0,
                             const float* __restrict__ W1,
                             const float* __restrict__ W2) {
    int i = blockIdx.x * blockDim.x + threadIdx.x;   // i = k*D + n (coalesced reads)
    if (i < D * D) {
        int k = i >> 8, n = i & 255;
        float v = (W0[i] + W1[i] + W2[i]) * (1.0f / 3.0f);
        g_w16t[n * D + k] = __float2half_rn(v);
    }
}

// ---------------- fp32 -> fp16 conversion of feat ---------------------------
__global__ void tohalf_kernel(const float* __restrict__ feat, int total2) {
    int i = blockIdx.x * blockDim.x + threadIdx.x;
    if (i < total2) {
        float2 v = ((const float2*)feat)[i];
        g_feat16[i] = __floats2half2_rn(v.x, v.y);
    }
}

// ---------------- zero degree counters --------------------------------------
__global__ void zero_kernel(int N) {
    int i = blockIdx.x * blockDim.x + threadIdx.x;
    if (i < 3 * N) g_deg[i] = 0;
}

// ---------------- histogram of dst per relation -----------------------------
__global__ void hist_kernel(const int* __restrict__ d0,
                            const int* __restrict__ d1,
                            const int* __restrict__ d2, int N, int E) {
    int i = blockIdx.x * blockDim.x + threadIdx.x;
    if (i >= 3 * E) return;
    int r = i / E, e = i - r * E;
    const int* ds = (r == 0) ? d0 : (r == 1) ? d1 : d2;
    atomicAdd(&g_deg[r * N + ds[e]], 1);
}

// ---------------- multi-block exclusive scan, phase 1 -----------------------
__global__ __launch_bounds__(SCAN_B) void scan_phase1(int total) {
    __shared__ int warpsum[SCAN_B / 32];
    int tid = threadIdx.x;
    int lane = tid & 31;
    int wid = tid >> 5;
    int i = blockIdx.x * SCAN_B + tid;
    int v = (i < total) ? g_deg[i] : 0;

    int incl = v;
    #pragma unroll
    for (int o = 1; o < 32; o <<= 1) {
        int t = __shfl_up_sync(0xffffffffu, incl, o);
        if (lane >= o) incl += t;
    }
    if (lane == 31) warpsum[wid] = incl;
    __syncthreads();
    if (wid == 0) {
        int w = (lane < SCAN_B / 32) ? warpsum[lane] : 0;
        #pragma unroll
        for (int o = 1; o < 32; o <<= 1) {
            int t = __shfl_up_sync(0xffffffffu, w, o);
            if (lane >= o) w += t;
        }
        if (lane < SCAN_B / 32) warpsum[lane] = w;
    }
    __syncthreads();
    int warpoff = (wid == 0) ? 0 : warpsum[wid - 1];
    int excl = warpoff + incl - v;
    if (i < total) g_offs[i] = excl;
    if (tid == SCAN_B - 1) g_blocksum[blockIdx.x] = excl + v;
}

// ---------------- phase 2: scan block sums -----------------------------------
__global__ __launch_bounds__(1024) void scan_phase2(int nblocks) {
    __shared__ int warpsum[32];
    int tid = threadIdx.x;
    int lane = tid & 31;
    int wid = tid >> 5;
    int v = (tid < nblocks) ? g_blocksum[tid] : 0;
    int incl = v;
    #pragma unroll
    for (int o = 1; o < 32; o <<= 1) {
        int t = __shfl_up_sync(0xffffffffu, incl, o);
        if (lane >= o) incl += t;
    }
    if (lane == 31) warpsum[wid] = incl;
    __syncthreads();
    if (wid == 0) {
        int w = warpsum[lane];
        #pragma unroll
        for (int o = 1; o < 32; o <<= 1) {
            int t = __shfl_up_sync(0xffffffffu, w, o);
            if (lane >= o) w += t;
        }
        warpsum[lane] = w;
    }
    __syncthreads();
    int warpoff = (wid == 0) ? 0 : warpsum[wid - 1];
    if (tid < nblocks) g_blockoff[tid] = warpoff + incl - v;
}

// ---------------- phase 3: add block offsets; init cursor --------------------
__global__ void scan_phase3(int total) {
    int i = blockIdx.x * SCAN_B + threadIdx.x;
    if (i >= total) return;
    int o = g_offs[i] + g_blockoff[blockIdx.x];
    g_offs[i] = o;
    g_cur[i] = o;
}

// ---------------- scatter edge srcs into CSR buckets ------------------------
__global__ void scatter_kernel(const int* __restrict__ s0, const int* __restrict__ d0,
                               const int* __restrict__ s1, const int* __restrict__ d1,
                               const int* __restrict__ s2, const int* __restrict__ d2,
                               int N, int E) {
    int i = blockIdx.x * blockDim.x + threadIdx.x;
    if (i >= 3 * E) return;
    int r = i / E, e = i - r * E;
    const int* ss = (r == 0) ? s0 : (r == 1) ? s1 : s2;
    const int* ds = (r == 0) ? d0 : (r == 1) ? d1 : d2;
    int node = r * N + ds[e];
    int p = atomicAdd(&g_cur[node], 1);
    g_bucket[p] = ss[e];
}

// ---------------- aggregate: warp per node, fp16 rows, fp32 accumulate ------
// Output written directly in fp16 (GEMM A operand).
__global__ void agg_kernel(int N) {
    int gwarp = (blockIdx.x * blockDim.x + threadIdx.x) >> 5;
    int lane = threadIdx.x & 31;
    if (gwarp >= N) return;
    float acc[8] = {0.f, 0.f, 0.f, 0.f, 0.f, 0.f, 0.f, 0.f};
    #pragma unroll
    for (int r = 0; r < 3; r++) {
        int idx = r * N + gwarp;
        int off = g_offs[idx];
        int dg = g_deg[idx];
        float s[8] = {0.f, 0.f, 0.f, 0.f, 0.f, 0.f, 0.f, 0.f};
        for (int e = 0; e < dg; e++) {
            int src = g_bucket[off + e];
            const int4* row = (const int4*)(g_feat16 + (size_t)src * (D / 2));
            int4 v = row[lane];
            __half2 h0 = *(__half2*)&v.x;
            __half2 h1 = *(__half2*)&v.y;
            __half2 h2 = *(__half2*)&v.z;
            __half2 h3 = *(__half2*)&v.w;
            float2 f0 = __half22float2(h0);
            float2 f1 = __half22float2(h1);
            float2 f2 = __half22float2(h2);
            float2 f3 = __half22float2(h3);
            s[0] += f0.x; s[1] += f0.y; s[2] += f1.x; s[3] += f1.y;
            s[4] += f2.x; s[5] += f2.y; s[6] += f3.x; s[7] += f3.y;
        }
        float sc = 1.0f / fmaxf((float)dg, 1.0f);
        #pragma unroll
        for (int k = 0; k < 8; k++) acc[k] += s[k] * sc;
    }
    const float third = 1.0f / 3.0f;
    __half2 o[4];
    #pragma unroll
    for (int k = 0; k < 4; k++)
        o[k] = __floats2half2_rn(acc[2 * k] * third, acc[2 * k + 1] * third);
    int4* orow = (int4*)(g_afeat16 + (size_t)gwarp * D + lane * 8);
    *orow = *(int4*)o;
}

// ---------------- tensor-core GEMM + ReLU + LayerNorm ------------------------
// C[M,256] = A_fp16[M,256] @ B_fp16[256,256]; mma.sync m16n8k16, fp32 accum.
// Block: 64 rows, 8 warps. Warp w: M-chunk (w&3)*16, N-half (w>>2)*128.
#define AST 18   // As row stride in halfs (padding kills bank conflicts)
#define BST 18   // Bs row stride in halfs

__device__ __forceinline__ void mma16816(float* d, const unsigned* a,
                                         const unsigned* b, const float* c) {
    asm volatile(
        "mma.sync.aligned.m16n8k16.row.col.f32.f16.f16.f32 "
        "{%0,%1,%2,%3}, {%4,%5,%6,%7}, {%8,%9}, {%10,%11,%12,%13};\n"
        : "=f"(d[0]), "=f"(d[1]), "=f"(d[2]), "=f"(d[3])
        : "r"(a[0]), "r"(a[1]), "r"(a[2]), "r"(a[3]),
          "r"(b[0]), "r"(b[1]),
          "f"(c[0]), "f"(c[1]), "f"(c[2]), "f"(c[3]));
}

__global__ __launch_bounds__(256) void gemm_ln_tc(const float* __restrict__ gamma,
                                                  const float* __restrict__ beta,
                                                  float* __restrict__ out, int M) {
    __shared__ __half As[64 * AST];
    __shared__ __half Bs[256 * BST];
    __shared__ float2 sred[2][4][16];

    int tid = threadIdx.x;
    int wid = tid >> 5;
    int lane = tid & 31;
    int g = lane >> 2;       // group id 0..7
    int t = lane & 3;        // thread-in-group 0..3
    int mchunk = wid & 3;    // 16-row chunk within block
    int nhalf = wid >> 2;    // 0 or 1 -> cols 0..127 / 128..255
    int rowBase = blockIdx.x * 64;

    float cacc[16][4];
    #pragma unroll
    for (int i = 0; i < 16; i++)
        #pragma unroll
        for (int j = 0; j < 4; j++) cacc[i][j] = 0.f;

    // A-tile loader coords: thread -> (row, b32 unit pair)
    int aRow = tid >> 2;            // 0..63
    int aU0 = (tid & 3) * 2;        // b32 units {aU0, aU0+1} of 8 per row
    bool aValid = (rowBase + aRow) < M;
    const unsigned* aSrc = (const unsigned*)(g_afeat16 + (size_t)(rowBase + aRow) * D);

    // B-tile loader coords
    int bN0 = tid >> 3;             // 0..31 (+32 per pass)
    int bU = tid & 7;               // b32 unit 0..7

    for (int k0 = 0; k0 < D; k0 += 16) {
        // load A tile 64x16
        #pragma unroll
        for (int j = 0; j < 2; j++) {
            int u = aU0 + j;
            unsigned v = aValid ? aSrc[(k0 >> 1) + u] : 0u;
            *(unsigned*)&As[aRow * AST + 2 * u] = v;
        }
        // load B tile 256x16 (from transposed fp16 weights)
        #pragma unroll
        for (int p = 0; p < 8; p++) {
            int n = bN0 + 32 * p;
            *(unsigned*)&Bs[n * BST + 2 * bU] =
                *(const unsigned*)(g_w16t + n * D + k0 + 2 * bU);
        }
        __syncthreads();

        // A fragment for this warp's 16-row chunk
        unsigned a[4];
        const __half* ab = &As[(mchunk * 16) * AST];
        a[0] = *(const unsigned*)&ab[g * AST + 2 * t];
        a[1] = *(const unsigned*)&ab[(g + 8) * AST + 2 * t];
        a[2] = *(const unsigned*)&ab[g * AST + 2 * t + 8];
        a[3] = *(const unsigned*)&ab[(g + 8) * AST + 2 * t + 8];

        #pragma unroll
        for (int nt = 0; nt < 16; nt++) {
            int n = nhalf * 128 + nt * 8 + g;
            unsigned b[2];
            b[0] = *(const unsigned*)&Bs[n * BST + 2 * t];
            b[1] = *(const unsigned*)&Bs[n * BST + 2 * t + 8];
            mma16816(cacc[nt], a, b, cacc[nt]);
        }
        __syncthreads();
    }

    // ---- fused ReLU + LayerNorm epilogue ------------------------------------
    float s0 = 0.f, ss0 = 0.f, s1 = 0.f, ss1 = 0.f;
    #pragma unroll
    for (int nt = 0; nt < 16; nt++) {
        float c0 = fmaxf(cacc[nt][0], 0.f);
        float c1 = fmaxf(cacc[nt][1], 0.f);
        float c2 = fmaxf(cacc[nt][2], 0.f);
        float c3 = fmaxf(cacc[nt][3], 0.f);
        cacc[nt][0] = c0; cacc[nt][1] = c1; cacc[nt][2] = c2; cacc[nt][3] = c3;
        s0 += c0 + c1; ss0 += c0 * c0 + c1 * c1;
        s1 += c2 + c3; ss1 += c2 * c2 + c3 * c3;
    }
    #pragma unroll
    for (int o = 1; o <= 2; o <<= 1) {
        s0 += __shfl_xor_sync(0xffffffffu, s0, o);
        ss0 += __shfl_xor_sync(0xffffffffu, ss0, o);
        s1 += __shfl_xor_sync(0xffffffffu, s1, o);
        ss1 += __shfl_xor_sync(0xffffffffu, ss1, o);
    }
    if (t == 0) {
        sred[nhalf][mchunk][g] = make_float2(s0, ss0);
        sred[nhalf][mchunk][g + 8] = make_float2(s1, ss1);
    }
    __syncthreads();
    float2 u0 = sred[0][mchunk][g], v0 = sred[1][mchunk][g];
    float2 u1 = sred[0][mchunk][g + 8], v1 = sred[1][mchunk][g + 8];
    float mu0 = (u0.x + v0.x) * (1.0f / D);
    float var0 = (u0.y + v0.y) * (1.0f / D) - mu0 * mu0;
    float rs0 = rsqrtf(var0 + LN_EPS);
    float mu1 = (u1.x + v1.x) * (1.0f / D);
    float var1 = (u1.y + v1.y) * (1.0f / D) - mu1 * mu1;
    float rs1 = rsqrtf(var1 + LN_EPS);

    int gr0 = rowBase + mchunk * 16 + g;
    int gr1 = gr0 + 8;
    #pragma unroll
    for (int nt = 0; nt < 16; nt++) {
        int col = nhalf * 128 + nt * 8 + 2 * t;
        float2 gm = *(const float2*)(gamma + col);
        float2 bt = *(const float2*)(beta + col);
        if (gr0 < M) {
            float2 o0;
            o0.x = (cacc[nt][0] - mu0) * rs0 * gm.x + bt.x;
            o0.y = (cacc[nt][1] - mu0) * rs0 * gm.y + bt.y;
            *(float2*)(out + (size_t)gr0 * D + col) = o0;
        }
        if (gr1 < M) {
            float2 o1;
            o1.x = (cacc[nt][2] - mu1) * rs1 * gm.x + bt.x;
            o1.y = (cacc[nt][3] - mu1) * rs1 * gm.y + bt.y;
            *(float2*)(out + (size_t)gr1 * D + col) = o1;
        }
    }
}

// ---------------- launch ----------------------------------------------------
extern "C" void kernel_launch(void* const* d_in, const int* in_sizes, int n_in,
                              void* d_out, int out_size) {
    const float* feat = (const float*)d_in[0];
    const float* W0 = (const float*)d_in[1];
    const float* W1 = (const float*)d_in[2];
    const float* W2 = (const float*)d_in[3];
    // d_in[4..6] = a0,a1,a2: softmax over size-1 tensors is identically 1,
    // so the mixing weights are always [1/3,1/3,1/3] independent of values.
    const float* gamma = (const float*)d_in[7];
    const float* beta = (const float*)d_in[8];
    const int* src0 = (const int*)d_in[9];
    const int* dst0 = (const int*)d_in[10];
    const int* src1 = (const int*)d_in[11];
    const int* dst1 = (const int*)d_in[12];
    const int* src2 = (const int*)d_in[13];
    const int* dst2 = (const int*)d_in[14];
    float* out = (float*)d_out;

    int N = in_sizes[0] / D;
    int E = in_sizes[9];
    int total = 3 * N;
    int nblocks = (total + SCAN_B - 1) / SCAN_B;
    int total2 = N * D / 2;

    wsumT_kernel<<<(D * D + 255) / 256, 256>>>(W0, W1, W2);
    tohalf_kernel<<<(total2 + 255) / 256, 256>>>(feat, total2);
    zero_kernel<<<(total + 255) / 256, 256>>>(N);
    hist_kernel<<<(3 * E + 255) / 256, 256>>>(dst0, dst1, dst2, N, E);
    scan_phase1<<<nblocks, SCAN_B>>>(total);
    scan_phase2<<<1, 1024>>>(nblocks);
    scan_phase3<<<nblocks, SCAN_B>>>(total);
    scatter_kernel<<<(3 * E + 255) / 256, 256>>>(src0, dst0, src1, dst1, src2, dst2, N, E);
    agg_kernel<<<(N + 7) / 8, 256>>>(N);
    gemm_ln_tc<<<(N + 63) / 64, 256>>>(gamma, beta, out, N);
}

// round 6
// speedup vs baseline: 2.8154x; 1.0234x over previous
#include <cuda_runtime.h>
#include <cuda_fp16.h>

#define D 256
#define MAXN 50048
#define MAXE 400256
#define LN_EPS 1e-5f
#define SCAN_B 1024

// ---------------- scratch (static device globals; no allocation) ------------
__device__ __half  g_w16t[D * D];          // (W0+W1+W2)/3, TRANSPOSED [n][k], fp16
__device__ __half  g_afeat16[MAXN * D];    // aggregated features, fp16 (GEMM A)
__device__ __half2 g_feat16[MAXN * D / 2]; // fp16 copy of feat for the gather
__device__ int     g_deg[3 * MAXN];
__device__ int     g_offs[3 * MAXN];
__device__ int     g_cur[3 * MAXN];
__device__ int     g_bucket[3 * MAXE];
__device__ int     g_scan_state[256];      // 0 none, 1 agg ready, 2 prefix ready
__device__ int     g_scan_agg[256];
__device__ int     g_scan_pref[256];

// ---------------- fused prep: Wsum^T fp16, feat->fp16, zero deg/state -------
__global__ void prep_kernel(const float* __restrict__ feat,
                            const float* __restrict__ W0,
                            const float* __restrict__ W1,
                            const float* __restrict__ W2,
                            int N, int total2) {
    int i = blockIdx.x * blockDim.x + threadIdx.x;
    if (i < total2) {
        float2 v = ((const float2*)feat)[i];
        g_feat16[i] = __floats2half2_rn(v.x, v.y);
    }
    if (i < D * D) {
        int k = i >> 8, n = i & 255;
        float v = (W0[i] + W1[i] + W2[i]) * (1.0f / 3.0f);
        g_w16t[n * D + k] = __float2half_rn(v);
    }
    if (i < 3 * N) g_deg[i] = 0;
    if (i < 256) g_scan_state[i] = 0;
}

// ---------------- histogram of dst per relation -----------------------------
__global__ void hist_kernel(const int* __restrict__ d0,
                            const int* __restrict__ d1,
                            const int* __restrict__ d2, int N, int E) {
    int i = blockIdx.x * blockDim.x + threadIdx.x;
    if (i >= 3 * E) return;
    int r = i / E, e = i - r * E;
    const int* ds = (r == 0) ? d0 : (r == 1) ? d1 : d2;
    atomicAdd(&g_deg[r * N + ds[e]], 1);
}

// ---------------- single-kernel decoupled-lookback exclusive scan -----------
// Requires grid <= #SMs so all blocks are co-resident (147 <= 148).
__global__ __launch_bounds__(SCAN_B) void scan_kernel(int total) {
    __shared__ int warpsum[SCAN_B / 32];
    __shared__ int s_prefix;
    int tid = threadIdx.x;
    int lane = tid & 31;
    int wid = tid >> 5;
    int b = blockIdx.x;
    int i = b * SCAN_B + tid;
    int v = (i < total) ? g_deg[i] : 0;

    // block-local exclusive scan
    int incl = v;
    #pragma unroll
    for (int o = 1; o < 32; o <<= 1) {
        int t = __shfl_up_sync(0xffffffffu, incl, o);
        if (lane >= o) incl += t;
    }
    if (lane == 31) warpsum[wid] = incl;
    __syncthreads();
    if (wid == 0) {
        int w = warpsum[lane];
        #pragma unroll
        for (int o = 1; o < 32; o <<= 1) {
            int t = __shfl_up_sync(0xffffffffu, w, o);
            if (lane >= o) w += t;
        }
        warpsum[lane] = w;   // inclusive over warps
    }
    __syncthreads();
    int warpoff = (wid == 0) ? 0 : warpsum[wid - 1];
    int excl = warpoff + incl - v;
    int blocksum = warpsum[SCAN_B / 32 - 1];

    // publish aggregate
    if (tid == 0) {
        g_scan_agg[b] = blocksum;
        __threadfence();
        atomicExch(&g_scan_state[b], 1);
        if (b == 0) {
            g_scan_pref[0] = blocksum;
            __threadfence();
            atomicExch(&g_scan_state[0], 2);
            s_prefix = 0;
        }
    }
    // warp 0 lookback (b > 0)
    if (b > 0 && wid == 0) {
        int running = 0;
        int j = b - 1;
        while (true) {
            int jj = j - lane;
            int st = 0, val = 0;
            if (jj >= 0) {
                do { st = atomicAdd(&g_scan_state[jj], 0); } while (st == 0);
                __threadfence();
                val = (st == 2) ? atomicAdd(&g_scan_pref[jj], 0)
                                : atomicAdd(&g_scan_agg[jj], 0);
            }
            unsigned pmask = __ballot_sync(0xffffffffu, (jj >= 0) && (st == 2));
            if (pmask) {
                int fl = __ffs(pmask) - 1;            // closest predecessor w/ prefix
                int contrib = (lane <= fl) ? val : 0;
                #pragma unroll
                for (int o = 16; o > 0; o >>= 1)
                    contrib += __shfl_xor_sync(0xffffffffu, contrib, o);
                running += contrib;
                break;
            } else {
                int contrib = (jj >= 0) ? val : 0;
                #pragma unroll
                for (int o = 16; o > 0; o >>= 1)
                    contrib += __shfl_xor_sync(0xffffffffu, contrib, o);
                running += contrib;
                if (j < 32) break;                    // window reached block 0
                j -= 32;
            }
        }
        if (lane == 0) {
            s_prefix = running;
            g_scan_pref[b] = running + blocksum;
            __threadfence();
            atomicExch(&g_scan_state[b], 2);
        }
    }
    __syncthreads();
    if (i < total) {
        int o = s_prefix + excl;
        g_offs[i] = o;
        g_cur[i] = o;
    }
}

// ---------------- scatter edge srcs into CSR buckets ------------------------
__global__ void scatter_kernel(const int* __restrict__ s0, const int* __restrict__ d0,
                               const int* __restrict__ s1, const int* __restrict__ d1,
                               const int* __restrict__ s2, const int* __restrict__ d2,
                               int N, int E) {
    int i = blockIdx.x * blockDim.x + threadIdx.x;
    if (i >= 3 * E) return;
    int r = i / E, e = i - r * E;
    const int* ss = (r == 0) ? s0 : (r == 1) ? s1 : s2;
    const int* ds = (r == 0) ? d0 : (r == 1) ? d1 : d2;
    int node = r * N + ds[e];
    int p = atomicAdd(&g_cur[node], 1);
    g_bucket[p] = ss[e];
}

// ---------------- aggregate: warp per node, fp16 rows, fp32 accumulate ------
__global__ void agg_kernel(int N) {
    int gwarp = (blockIdx.x * blockDim.x + threadIdx.x) >> 5;
    int lane = threadIdx.x & 31;
    if (gwarp >= N) return;
    float acc[8] = {0.f, 0.f, 0.f, 0.f, 0.f, 0.f, 0.f, 0.f};
    #pragma unroll
    for (int r = 0; r < 3; r++) {
        int idx = r * N + gwarp;
        int off = g_offs[idx];
        int dg = g_deg[idx];
        float s[8] = {0.f, 0.f, 0.f, 0.f, 0.f, 0.f, 0.f, 0.f};
        for (int e = 0; e < dg; e++) {
            int src = g_bucket[off + e];
            const int4* row = (const int4*)(g_feat16 + (size_t)src * (D / 2));
            int4 v = row[lane];
            __half2 h0 = *(__half2*)&v.x;
            __half2 h1 = *(__half2*)&v.y;
            __half2 h2 = *(__half2*)&v.z;
            __half2 h3 = *(__half2*)&v.w;
            float2 f0 = __half22float2(h0);
            float2 f1 = __half22float2(h1);
            float2 f2 = __half22float2(h2);
            float2 f3 = __half22float2(h3);
            s[0] += f0.x; s[1] += f0.y; s[2] += f1.x; s[3] += f1.y;
            s[4] += f2.x; s[5] += f2.y; s[6] += f3.x; s[7] += f3.y;
        }
        float sc = 1.0f / fmaxf((float)dg, 1.0f);
        #pragma unroll
        for (int k = 0; k < 8; k++) acc[k] += s[k] * sc;
    }
    const float third = 1.0f / 3.0f;
    __half2 o[4];
    #pragma unroll
    for (int k = 0; k < 4; k++)
        o[k] = __floats2half2_rn(acc[2 * k] * third, acc[2 * k + 1] * third);
    int4* orow = (int4*)(g_afeat16 + (size_t)gwarp * D + lane * 8);
    *orow = *(int4*)o;
}

// ---------------- tensor-core GEMM + ReLU + LayerNorm ------------------------
// C[M,256] = A_fp16[M,256] @ B_fp16[256,256]; mma.sync m16n8k16, fp32 accum.
// Block: 128 rows, 16 warps (512 thr). Warp w: M-chunk (w&7)*16, N-half (w>>3)*128.
#define AST 18
#define BST 18

__device__ __forceinline__ void mma16816(float* d, const unsigned* a,
                                         const unsigned* b, const float* c) {
    asm volatile(
        "mma.sync.aligned.m16n8k16.row.col.f32.f16.f16.f32 "
        "{%0,%1,%2,%3}, {%4,%5,%6,%7}, {%8,%9}, {%10,%11,%12,%13};\n"
        : "=f"(d[0]), "=f"(d[1]), "=f"(d[2]), "=f"(d[3])
        : "r"(a[0]), "r"(a[1]), "r"(a[2]), "r"(a[3]),
          "r"(b[0]), "r"(b[1]),
          "f"(c[0]), "f"(c[1]), "f"(c[2]), "f"(c[3]));
}

__global__ __launch_bounds__(512) void gemm_ln_tc(const float* __restrict__ gamma,
                                                  const float* __restrict__ beta,
                                                  float* __restrict__ out, int M) {
    __shared__ __half As[128 * AST];
    __shared__ __half Bs[256 * BST];
    __shared__ float2 sred[2][8][16];

    int tid = threadIdx.x;
    int wid = tid >> 5;
    int lane = tid & 31;
    int g = lane >> 2;       // group id 0..7
    int t = lane & 3;        // thread-in-group 0..3
    int mchunk = wid & 7;    // 16-row chunk within block
    int nhalf = wid >> 3;    // 0 or 1 -> cols 0..127 / 128..255
    int rowBase = blockIdx.x * 128;

    float cacc[16][4];
    #pragma unroll
    for (int i = 0; i < 16; i++)
        #pragma unroll
        for (int j = 0; j < 4; j++) cacc[i][j] = 0.f;

    // A-tile loader: 512 threads cover 128 rows x 8 b32-units (2 units each)
    int aRow = tid >> 2;            // 0..127
    int aU0 = (tid & 3) * 2;        // units {aU0, aU0+1}
    bool aValid = (rowBase + aRow) < M;
    const unsigned* aSrc = (const unsigned*)(g_afeat16 + (size_t)(rowBase + aRow) * D);

    // B-tile loader: 512 threads cover 256 n x 8 units (4 n-passes)
    int bN0 = tid >> 3;             // 0..63
    int bU = tid & 7;

    for (int k0 = 0; k0 < D; k0 += 16) {
        #pragma unroll
        for (int j = 0; j < 2; j++) {
            int u = aU0 + j;
            unsigned v = aValid ? aSrc[(k0 >> 1) + u] : 0u;
            *(unsigned*)&As[aRow * AST + 2 * u] = v;
        }
        #pragma unroll
        for (int p = 0; p < 4; p++) {
            int n = bN0 + 64 * p;
            *(unsigned*)&Bs[n * BST + 2 * bU] =
                *(const unsigned*)(g_w16t + n * D + k0 + 2 * bU);
        }
        __syncthreads();

        unsigned a[4];
        const __half* ab = &As[(mchunk * 16) * AST];
        a[0] = *(const unsigned*)&ab[g * AST + 2 * t];
        a[1] = *(const unsigned*)&ab[(g + 8) * AST + 2 * t];
        a[2] = *(const unsigned*)&ab[g * AST + 2 * t + 8];
        a[3] = *(const unsigned*)&ab[(g + 8) * AST + 2 * t + 8];

        #pragma unroll
        for (int nt = 0; nt < 16; nt++) {
            int n = nhalf * 128 + nt * 8 + g;
            unsigned b[2];
            b[0] = *(const unsigned*)&Bs[n * BST + 2 * t];
            b[1] = *(const unsigned*)&Bs[n * BST + 2 * t + 8];
            mma16816(cacc[nt], a, b, cacc[nt]);
        }
        __syncthreads();
    }

    // ---- fused ReLU + LayerNorm epilogue ------------------------------------
    float s0 = 0.f, ss0 = 0.f, s1 = 0.f, ss1 = 0.f;
    #pragma unroll
    for (int nt = 0; nt < 16; nt++) {
        float c0 = fmaxf(cacc[nt][0], 0.f);
        float c1 = fmaxf(cacc[nt][1], 0.f);
        float c2 = fmaxf(cacc[nt][2], 0.f);
        float c3 = fmaxf(cacc[nt][3], 0.f);
        cacc[nt][0] = c0; cacc[nt][1] = c1; cacc[nt][2] = c2; cacc[nt][3] = c3;
        s0 += c0 + c1; ss0 += c0 * c0 + c1 * c1;
        s1 += c2 + c3; ss1 += c2 * c2 + c3 * c3;
    }
    #pragma unroll
    for (int o = 1; o <= 2; o <<= 1) {
        s0 += __shfl_xor_sync(0xffffffffu, s0, o);
        ss0 += __shfl_xor_sync(0xffffffffu, ss0, o);
        s1 += __shfl_xor_sync(0xffffffffu, s1, o);
        ss1 += __shfl_xor_sync(0xffffffffu, ss1, o);
    }
    if (t == 0) {
        sred[nhalf][mchunk][g] = make_float2(s0, ss0);
        sred[nhalf][mchunk][g + 8] = make_float2(s1, ss1);
    }
    __syncthreads();
    float2 u0 = sred[0][mchunk][g], v0 = sred[1][mchunk][g];
    float2 u1 = sred[0][mchunk][g + 8], v1 = sred[1][mchunk][g + 8];
    float mu0 = (u0.x + v0.x) * (1.0f / D);
    float var0 = (u0.y + v0.y) * (1.0f / D) - mu0 * mu0;
    float rs0 = rsqrtf(var0 + LN_EPS);
    float mu1 = (u1.x + v1.x) * (1.0f / D);
    float var1 = (u1.y + v1.y) * (1.0f / D) - mu1 * mu1;
    float rs1 = rsqrtf(var1 + LN_EPS);

    int gr0 = rowBase + mchunk * 16 + g;
    int gr1 = gr0 + 8;
    #pragma unroll
    for (int nt = 0; nt < 16; nt++) {
        int col = nhalf * 128 + nt * 8 + 2 * t;
        float2 gm = *(const float2*)(gamma + col);
        float2 bt = *(const float2*)(beta + col);
        if (gr0 < M) {
            float2 o0;
            o0.x = (cacc[nt][0] - mu0) * rs0 * gm.x + bt.x;
            o0.y = (cacc[nt][1] - mu0) * rs0 * gm.y + bt.y;
            *(float2*)(out + (size_t)gr0 * D + col) = o0;
        }
        if (gr1 < M) {
            float2 o1;
            o1.x = (cacc[nt][2] - mu1) * rs1 * gm.x + bt.x;
            o1.y = (cacc[nt][3] - mu1) * rs1 * gm.y + bt.y;
            *(float2*)(out + (size_t)gr1 * D + col) = o1;
        }
    }
}

// ---------------- launch ----------------------------------------------------
extern "C" void kernel_launch(void* const* d_in, const int* in_sizes, int n_in,
                              void* d_out, int out_size) {
    const float* feat = (const float*)d_in[0];
    const float* W0 = (const float*)d_in[1];
    const float* W1 = (const float*)d_in[2];
    const float* W2 = (const float*)d_in[3];
    // d_in[4..6] = a0,a1,a2: softmax over size-1 tensors is identically 1,
    // so the mixing weights are always [1/3,1/3,1/3] independent of values.
    const float* gamma = (const float*)d_in[7];
    const float* beta = (const float*)d_in[8];
    const int* src0 = (const int*)d_in[9];
    const int* dst0 = (const int*)d_in[10];
    const int* src1 = (const int*)d_in[11];
    const int* dst1 = (const int*)d_in[12];
    const int* src2 = (const int*)d_in[13];
    const int* dst2 = (const int*)d_in[14];
    float* out = (float*)d_out;

    int N = in_sizes[0] / D;
    int E = in_sizes[9];
    int total = 3 * N;
    int nblocks = (total + SCAN_B - 1) / SCAN_B;
    int total2 = N * D / 2;

    prep_kernel<<<(total2 + 255) / 256, 256>>>(feat, W0, W1, W2, N, total2);
    hist_kernel<<<(3 * E + 255) / 256, 256>>>(dst0, dst1, dst2, N, E);
    scan_kernel<<<nblocks, SCAN_B>>>(total);
    scatter_kernel<<<(3 * E + 255) / 256, 256>>>(src0, dst0, src1, dst1, src2, dst2, N, E);
    agg_kernel<<<(N + 7) / 8, 256>>>(N);
    gemm_ln_tc<<<(N + 127) / 128, 512>>>(gamma, beta, out, N);
}

// round 8
// speedup vs baseline: 3.4179x; 1.2140x over previous
#include <cuda_runtime.h>
#include <cuda_fp16.h>

#define D 256
#define MAXN 50048
#define MAXE 400256
#define LN_EPS 1e-5f
#define SCAN_B 1024

// ---------------- scratch (static device globals; no allocation) ------------
__device__ __half  g_w16t[D * D];          // (W0+W1+W2)/3, TRANSPOSED [n][k], fp16
__device__ __half  g_afeat16[MAXN * D];    // aggregated features, fp16 (GEMM A)
__device__ __half2 g_feat16[MAXN * D / 2]; // fp16 copy of feat for the gather
__device__ int     g_deg[3 * MAXN];
__device__ int     g_offs[3 * MAXN];
__device__ int     g_cur[3 * MAXN];
__device__ int     g_bucket[3 * MAXE];
__device__ int     g_scan_state[256];      // 0 none, 1 agg ready, 2 prefix ready
__device__ int     g_scan_agg[256];
__device__ int     g_scan_pref[256];

// ---------------- conversion: feat->fp16, Wsum^T->fp16 (side stream) --------
__global__ void conv_kernel(const float* __restrict__ feat,
                            const float* __restrict__ W0,
                            const float* __restrict__ W1,
                            const float* __restrict__ W2,
                            int total2) {
    int i = blockIdx.x * blockDim.x + threadIdx.x;
    if (i < total2) {
        float2 v = ((const float2*)feat)[i];
        g_feat16[i] = __floats2half2_rn(v.x, v.y);
    }
    if (i < D * D) {
        int k = i >> 8, n = i & 255;
        float v = (W0[i] + W1[i] + W2[i]) * (1.0f / 3.0f);
        g_w16t[n * D + k] = __float2half_rn(v);
    }
}

// ---------------- zero degree counters + scan state --------------------------
__global__ void zero_kernel(int N) {
    int i = blockIdx.x * blockDim.x + threadIdx.x;
    if (i < 3 * N) g_deg[i] = 0;
    if (i < 256) g_scan_state[i] = 0;
}

// ---------------- histogram of dst per relation (4 edges/thread) -------------
__global__ void hist_kernel(const int* __restrict__ d0,
                            const int* __restrict__ d1,
                            const int* __restrict__ d2, int N, int E) {
    int base = (blockIdx.x * blockDim.x + threadIdx.x) * 4;
    #pragma unroll
    for (int u = 0; u < 4; u++) {
        int i = base + u;
        if (i >= 3 * E) break;
        int r = i / E, e = i - r * E;
        const int* ds = (r == 0) ? d0 : (r == 1) ? d1 : d2;
        atomicAdd(&g_deg[r * N + ds[e]], 1);
    }
}

// ---------------- single-kernel decoupled-lookback exclusive scan -----------
__global__ __launch_bounds__(SCAN_B) void scan_kernel(int total) {
    __shared__ int warpsum[SCAN_B / 32];
    __shared__ int s_prefix;
    int tid = threadIdx.x;
    int lane = tid & 31;
    int wid = tid >> 5;
    int b = blockIdx.x;
    int i = b * SCAN_B + tid;
    int v = (i < total) ? g_deg[i] : 0;

    int incl = v;
    #pragma unroll
    for (int o = 1; o < 32; o <<= 1) {
        int t = __shfl_up_sync(0xffffffffu, incl, o);
        if (lane >= o) incl += t;
    }
    if (lane == 31) warpsum[wid] = incl;
    __syncthreads();
    if (wid == 0) {
        int w = warpsum[lane];
        #pragma unroll
        for (int o = 1; o < 32; o <<= 1) {
            int t = __shfl_up_sync(0xffffffffu, w, o);
            if (lane >= o) w += t;
        }
        warpsum[lane] = w;
    }
    __syncthreads();
    int warpoff = (wid == 0) ? 0 : warpsum[wid - 1];
    int excl = warpoff + incl - v;
    int blocksum = warpsum[SCAN_B / 32 - 1];

    if (tid == 0) {
        g_scan_agg[b] = blocksum;
        __threadfence();
        atomicExch(&g_scan_state[b], 1);
        if (b == 0) {
            g_scan_pref[0] = blocksum;
            __threadfence();
            atomicExch(&g_scan_state[0], 2);
            s_prefix = 0;
        }
    }
    if (b > 0 && wid == 0) {
        int running = 0;
        int j = b - 1;
        while (true) {
            int jj = j - lane;
            int st = 0, val = 0;
            if (jj >= 0) {
                do { st = atomicAdd(&g_scan_state[jj], 0); } while (st == 0);
                __threadfence();
                val = (st == 2) ? atomicAdd(&g_scan_pref[jj], 0)
                                : atomicAdd(&g_scan_agg[jj], 0);
            }
            unsigned pmask = __ballot_sync(0xffffffffu, (jj >= 0) && (st == 2));
            if (pmask) {
                int fl = __ffs(pmask) - 1;
                int contrib = (lane <= fl) ? val : 0;
                #pragma unroll
                for (int o = 16; o > 0; o >>= 1)
                    contrib += __shfl_xor_sync(0xffffffffu, contrib, o);
                running += contrib;
                break;
            } else {
                int contrib = (jj >= 0) ? val : 0;
                #pragma unroll
                for (int o = 16; o > 0; o >>= 1)
                    contrib += __shfl_xor_sync(0xffffffffu, contrib, o);
                running += contrib;
                if (j < 32) break;
                j -= 32;
            }
        }
        if (lane == 0) {
            s_prefix = running;
            g_scan_pref[b] = running + blocksum;
            __threadfence();
            atomicExch(&g_scan_state[b], 2);
        }
    }
    __syncthreads();
    if (i < total) {
        int o = s_prefix + excl;
        g_offs[i] = o;
        g_cur[i] = o;
    }
}

// ---------------- scatter edge srcs into CSR buckets (4 edges/thread) --------
__global__ void scatter_kernel(const int* __restrict__ s0, const int* __restrict__ d0,
                               const int* __restrict__ s1, const int* __restrict__ d1,
                               const int* __restrict__ s2, const int* __restrict__ d2,
                               int N, int E) {
    int base = (blockIdx.x * blockDim.x + threadIdx.x) * 4;
    #pragma unroll
    for (int u = 0; u < 4; u++) {
        int i = base + u;
        if (i >= 3 * E) break;
        int r = i / E, e = i - r * E;
        const int* ss = (r == 0) ? s0 : (r == 1) ? s1 : s2;
        const int* ds = (r == 0) ? d0 : (r == 1) ? d1 : d2;
        int node = r * N + ds[e];
        int p = atomicAdd(&g_cur[node], 1);
        g_bucket[p] = ss[e];
    }
}

// ---------------- aggregate: warp per node, fp16 rows, fp32 accumulate ------
__global__ void agg_kernel(int N) {
    int gwarp = (blockIdx.x * blockDim.x + threadIdx.x) >> 5;
    int lane = threadIdx.x & 31;
    if (gwarp >= N) return;
    float acc[8] = {0.f, 0.f, 0.f, 0.f, 0.f, 0.f, 0.f, 0.f};
    #pragma unroll
    for (int r = 0; r < 3; r++) {
        int idx = r * N + gwarp;
        int off = g_offs[idx];
        int dg = g_deg[idx];
        float s[8] = {0.f, 0.f, 0.f, 0.f, 0.f, 0.f, 0.f, 0.f};
        for (int e = 0; e < dg; e++) {
            int src = g_bucket[off + e];
            const int4* row = (const int4*)(g_feat16 + (size_t)src * (D / 2));
            int4 v = row[lane];
            __half2 h0 = *(__half2*)&v.x;
            __half2 h1 = *(__half2*)&v.y;
            __half2 h2 = *(__half2*)&v.z;
            __half2 h3 = *(__half2*)&v.w;
            float2 f0 = __half22float2(h0);
            float2 f1 = __half22float2(h1);
            float2 f2 = __half22float2(h2);
            float2 f3 = __half22float2(h3);
            s[0] += f0.x; s[1] += f0.y; s[2] += f1.x; s[3] += f1.y;
            s[4] += f2.x; s[5] += f2.y; s[6] += f3.x; s[7] += f3.y;
        }
        float sc = 1.0f / fmaxf((float)dg, 1.0f);
        #pragma unroll
        for (int k = 0; k < 8; k++) acc[k] += s[k] * sc;
    }
    const float third = 1.0f / 3.0f;
    __half2 o[4];
    #pragma unroll
    for (int k = 0; k < 4; k++)
        o[k] = __floats2half2_rn(acc[2 * k] * third, acc[2 * k + 1] * third);
    int4* orow = (int4*)(g_afeat16 + (size_t)gwarp * D + lane * 8);
    *orow = *(int4*)o;
}

// ---------------- tensor-core GEMM + ReLU + LayerNorm ------------------------
// Full A-tile (128x256) and B (256x256) resident in smem; ONE sync, then
// 16 uninterrupted MMA k-steps. Block: 128 rows, 512 threads, 16 warps.
#define RST 264   // smem row stride in halfs (132 words: banks (4g+t)%32 distinct)
#define GEMM_SMEM (((128 + 256) * RST) * 2 + 2 * 8 * 16 * 8)

__device__ __forceinline__ void mma16816(float* d, const unsigned* a,
                                         const unsigned* b, const float* c) {
    asm volatile(
        "mma.sync.aligned.m16n8k16.row.col.f32.f16.f16.f32 "
        "{%0,%1,%2,%3}, {%4,%5,%6,%7}, {%8,%9}, {%10,%11,%12,%13};\n"
        : "=f"(d[0]), "=f"(d[1]), "=f"(d[2]), "=f"(d[3])
        : "r"(a[0]), "r"(a[1]), "r"(a[2]), "r"(a[3]),
          "r"(b[0]), "r"(b[1]),
          "f"(c[0]), "f"(c[1]), "f"(c[2]), "f"(c[3]));
}

__global__ __launch_bounds__(512) void gemm_ln_tc(const float* __restrict__ gamma,
                                                  const float* __restrict__ beta,
                                                  float* __restrict__ out, int M) {
    extern __shared__ __half smem[];
    __half* As = smem;                          // 128 x RST
    __half* Bs = smem + 128 * RST;              // 256 x RST
    float2* sred = (float2*)(smem + (128 + 256) * RST);  // [2][8][16]

    int tid = threadIdx.x;
    int wid = tid >> 5;
    int lane = tid & 31;
    int g = lane >> 2;
    int t = lane & 3;
    int mchunk = wid & 7;
    int nhalf = wid >> 3;
    int rowBase = blockIdx.x * 128;

    // ---- load full A tile: 128 rows x 32 int4 -------------------------------
    #pragma unroll
    for (int j = 0; j < 8; j++) {
        int l = tid + 512 * j;        // 0..4095
        int row = l >> 5;
        int unit = l & 31;
        int4 v = make_int4(0, 0, 0, 0);
        if (rowBase + row < M)
            v = *(const int4*)(g_afeat16 + (size_t)(rowBase + row) * D + unit * 8);
        *(int4*)&As[row * RST + unit * 8] = v;
    }
    // ---- load full B: 256 rows x 32 int4 ------------------------------------
    #pragma unroll
    for (int j = 0; j < 16; j++) {
        int l = tid + 512 * j;        // 0..8191
        int row = l >> 5;
        int unit = l & 31;
        *(int4*)&Bs[row * RST + unit * 8] =
            *(const int4*)(g_w16t + (size_t)row * D + unit * 8);
    }
    __syncthreads();

    float cacc[16][4];
    #pragma unroll
    for (int i = 0; i < 16; i++)
        #pragma unroll
        for (int j = 0; j < 4; j++) cacc[i][j] = 0.f;

    const __half* ab = &As[(mchunk * 16) * RST];
    #pragma unroll
    for (int kc = 0; kc < 16; kc++) {
        int kh = kc * 16;
        unsigned a[4];
        a[0] = *(const unsigned*)&ab[g * RST + kh + 2 * t];
        a[1] = *(const unsigned*)&ab[(g + 8) * RST + kh + 2 * t];
        a[2] = *(const unsigned*)&ab[g * RST + kh + 2 * t + 8];
        a[3] = *(const unsigned*)&ab[(g + 8) * RST + kh + 2 * t + 8];
        #pragma unroll
        for (int nt = 0; nt < 16; nt++) {
            int n = nhalf * 128 + nt * 8 + g;
            unsigned b[2];
            b[0] = *(const unsigned*)&Bs[n * RST + kh + 2 * t];
            b[1] = *(const unsigned*)&Bs[n * RST + kh + 2 * t + 8];
            mma16816(cacc[nt], a, b, cacc[nt]);
        }
    }

    // ---- fused ReLU + LayerNorm epilogue ------------------------------------
    float s0 = 0.f, ss0 = 0.f, s1 = 0.f, ss1 = 0.f;
    #pragma unroll
    for (int nt = 0; nt < 16; nt++) {
        float c0 = fmaxf(cacc[nt][0], 0.f);
        float c1 = fmaxf(cacc[nt][1], 0.f);
        float c2 = fmaxf(cacc[nt][2], 0.f);
        float c3 = fmaxf(cacc[nt][3], 0.f);
        cacc[nt][0] = c0; cacc[nt][1] = c1; cacc[nt][2] = c2; cacc[nt][3] = c3;
        s0 += c0 + c1; ss0 += c0 * c0 + c1 * c1;
        s1 += c2 + c3; ss1 += c2 * c2 + c3 * c3;
    }
    #pragma unroll
    for (int o = 1; o <= 2; o <<= 1) {
        s0 += __shfl_xor_sync(0xffffffffu, s0, o);
        ss0 += __shfl_xor_sync(0xffffffffu, ss0, o);
        s1 += __shfl_xor_sync(0xffffffffu, s1, o);
        ss1 += __shfl_xor_sync(0xffffffffu, ss1, o);
    }
    // sred layout: [nhalf][mchunk][rowIdx]
    if (t == 0) {
        sred[(nhalf * 8 + mchunk) * 16 + g] = make_float2(s0, ss0);
        sred[(nhalf * 8 + mchunk) * 16 + g + 8] = make_float2(s1, ss1);
    }
    __syncthreads();
    float2 u0 = sred[(0 * 8 + mchunk) * 16 + g];
    float2 v0 = sred[(1 * 8 + mchunk) * 16 + g];
    float2 u1 = sred[(0 * 8 + mchunk) * 16 + g + 8];
    float2 v1 = sred[(1 * 8 + mchunk) * 16 + g + 8];
    float mu0 = (u0.x + v0.x) * (1.0f / D);
    float var0 = (u0.y + v0.y) * (1.0f / D) - mu0 * mu0;
    float rs0 = rsqrtf(var0 + LN_EPS);
    float mu1 = (u1.x + v1.x) * (1.0f / D);
    float var1 = (u1.y + v1.y) * (1.0f / D) - mu1 * mu1;
    float rs1 = rsqrtf(var1 + LN_EPS);

    int gr0 = rowBase + mchunk * 16 + g;
    int gr1 = gr0 + 8;
    #pragma unroll
    for (int nt = 0; nt < 16; nt++) {
        int col = nhalf * 128 + nt * 8 + 2 * t;
        float2 gm = *(const float2*)(gamma + col);
        float2 bt = *(const float2*)(beta + col);
        if (gr0 < M) {
            float2 o0;
            o0.x = (cacc[nt][0] - mu0) * rs0 * gm.x + bt.x;
            o0.y = (cacc[nt][1] - mu0) * rs0 * gm.y + bt.y;
            *(float2*)(out + (size_t)gr0 * D + col) = o0;
        }
        if (gr1 < M) {
            float2 o1;
            o1.x = (cacc[nt][2] - mu1) * rs1 * gm.x + bt.x;
            o1.y = (cacc[nt][3] - mu1) * rs1 * gm.y + bt.y;
            *(float2*)(out + (size_t)gr1 * D + col) = o1;
        }
    }
}

// ---------------- launch ----------------------------------------------------
extern "C" void kernel_launch(void* const* d_in, const int* in_sizes, int n_in,
                              void* d_out, int out_size) {
    const float* feat = (const float*)d_in[0];
    const float* W0 = (const float*)d_in[1];
    const float* W1 = (const float*)d_in[2];
    const float* W2 = (const float*)d_in[3];
    // d_in[4..6] = a0,a1,a2: softmax over size-1 tensors is identically 1,
    // so the mixing weights are always [1/3,1/3,1/3] independent of values.
    const float* gamma = (const float*)d_in[7];
    const float* beta = (const float*)d_in[8];
    const int* src0 = (const int*)d_in[9];
    const int* dst0 = (const int*)d_in[10];
    const int* src1 = (const int*)d_in[11];
    const int* dst1 = (const int*)d_in[12];
    const int* src2 = (const int*)d_in[13];
    const int* dst2 = (const int*)d_in[14];
    float* out = (float*)d_out;

    int N = in_sizes[0] / D;
    int E = in_sizes[9];
    int total = 3 * N;
    int nblocks = (total + SCAN_B - 1) / SCAN_B;
    int total2 = N * D / 2;

    // one-time host objects (created on the uncaptured correctness call)
    static cudaStream_t s_side = nullptr;
    static cudaEvent_t s_fork = nullptr, s_join = nullptr;
    if (s_side == nullptr) {
        cudaStreamCreateWithFlags(&s_side, cudaStreamNonBlocking);
        cudaEventCreateWithFlags(&s_fork, cudaEventDisableTiming);
        cudaEventCreateWithFlags(&s_join, cudaEventDisableTiming);
        cudaFuncSetAttribute(gemm_ln_tc,
                             cudaFuncAttributeMaxDynamicSharedMemorySize, GEMM_SMEM);
    }

    // fork: fp16 conversions run concurrently with the CSR-build chain
    cudaEventRecord(s_fork, 0);
    cudaStreamWaitEvent(s_side, s_fork, 0);
    conv_kernel<<<(total2 + 255) / 256, 256, 0, s_side>>>(feat, W0, W1, W2, total2);
    cudaEventRecord(s_join, s_side);

    zero_kernel<<<(total + 1023) / 1024, 1024>>>(N);
    hist_kernel<<<(3 * E + 1023) / 1024, 256>>>(dst0, dst1, dst2, N, E);
    scan_kernel<<<nblocks, SCAN_B>>>(total);
    scatter_kernel<<<(3 * E + 1023) / 1024, 256>>>(src0, dst0, src1, dst1, src2, dst2, N, E);

    // join: agg needs g_feat16; gemm needs g_w16t
    cudaStreamWaitEvent(0, s_join, 0);
    agg_kernel<<<(N + 7) / 8, 256>>>(N);
    gemm_ln_tc<<<(N + 127) / 128, 512, GEMM_SMEM>>>(gamma, beta, out, N);
}